// round 5
// baseline (speedup 1.0000x reference)
#include <cuda_runtime.h>
#include <math_constants.h>
#include <cstdint>

// FCOS decode — cp.async.bulk (UBLKCP) staging of class logits, mbarrier ring.
//   inputs  : bbox [16,128,128,4] f32, center [16,128,128,1] f32, cls [16,128,128,80] f32
//   outputs : xywh [16,16384,4] f32 ++ cls_idx [16,16384] (as f32) ++ conf [16,16384] f32

#define N_LOC      (16 * 128 * 128)   // 262144
#define N_CLS      80
#define XYWH_ELEMS (N_LOC * 4)

#define THREADS        128
#define TILE           32                        // locations per pipeline stage
#define STAGES         3
#define F4_PER_ROW     (N_CLS / 4)               // 20
#define F4_PER_TILE    (TILE * F4_PER_ROW)       // 640
#define TILE_BYTES     (F4_PER_TILE * 16)        // 10240
#define N_TILES        (N_LOC / TILE)            // 8192

#define NUM_SMS        148
#define BLOCKS_PER_SM  7
#define GRID           (NUM_SMS * BLOCKS_PER_SM) // 1036

__device__ __forceinline__ unsigned smem_u32(const void* p) {
    return (unsigned)__cvta_generic_to_shared(p);
}
__device__ __forceinline__ void mbar_init(unsigned bar, unsigned count) {
    asm volatile("mbarrier.init.shared.b64 [%0], %1;" :: "r"(bar), "r"(count) : "memory");
}
__device__ __forceinline__ void mbar_expect_tx(unsigned bar, unsigned bytes) {
    asm volatile("mbarrier.arrive.expect_tx.shared.b64 _, [%0], %1;"
                 :: "r"(bar), "r"(bytes) : "memory");
}
__device__ __forceinline__ void bulk_g2s(unsigned dst, const void* src,
                                         unsigned bytes, unsigned bar) {
    asm volatile("cp.async.bulk.shared::cta.global.mbarrier::complete_tx::bytes "
                 "[%0], [%1], %2, [%3];"
                 :: "r"(dst), "l"(src), "r"(bytes), "r"(bar) : "memory");
}
__device__ __forceinline__ void mbar_wait(unsigned bar, unsigned parity) {
    asm volatile(
        "{\n\t"
        ".reg .pred P;\n\t"
        "WAIT_%=:\n\t"
        "mbarrier.try_wait.parity.shared.b64 P, [%0], %1, 0x989680;\n\t"
        "@P bra.uni DONE_%=;\n\t"
        "bra.uni WAIT_%=;\n\t"
        "DONE_%=:\n\t"
        "}"
        :: "r"(bar), "r"(parity) : "memory");
}

__global__ __launch_bounds__(THREADS)
void fcos_decode_kernel(const float* __restrict__ cls,
                        const float4* __restrict__ bbox4,
                        const float*  __restrict__ center,
                        float* __restrict__ out)
{
    __shared__ float4   sm[STAGES][F4_PER_TILE];     // 30 KB
    __shared__ uint64_t mbar[STAGES];

    const int t      = threadIdx.x;
    const int stride = gridDim.x;
    const int row    = t >> 2;   // 0..31 (location within tile)
    const int part   = t & 3;    // 0..3  (20-class segment)

    unsigned bar_u32[STAGES];
    #pragma unroll
    for (int s = 0; s < STAGES; ++s) bar_u32[s] = smem_u32(&mbar[s]);

    if (t == 0) {
        #pragma unroll
        for (int s = 0; s < STAGES; ++s) mbar_init(bar_u32[s], 1);
        asm volatile("fence.proxy.async.shared::cta;" ::: "memory");
    }
    __syncthreads();

    // ---- prologue: issue tiles for iterations 0..STAGES-2 ----
    if (t == 0) {
        #pragma unroll
        for (int s = 0; s < STAGES - 1; ++s) {
            long long tile = (long long)blockIdx.x + (long long)s * stride;
            if (tile < N_TILES) {
                mbar_expect_tx(bar_u32[s], TILE_BYTES);
                bulk_g2s(smem_u32(&sm[s][0]), cls + tile * (TILE * N_CLS),
                         TILE_BYTES, bar_u32[s]);
            }
        }
    }

    int buf = 0, phase = 0;
    long long issue_tile = (long long)blockIdx.x + (long long)(STAGES - 1) * stride;

    for (long long k = blockIdx.x; k < N_TILES; k += stride) {
        // ---- issue tile for iteration n+STAGES-1 into buf (buf+STAGES-1)%STAGES ----
        if (t == 0 && issue_tile < N_TILES) {
            int ibuf = buf + (STAGES - 1);
            if (ibuf >= STAGES) ibuf -= STAGES;
            mbar_expect_tx(bar_u32[ibuf], TILE_BYTES);
            bulk_g2s(smem_u32(&sm[ibuf][0]), cls + issue_tile * (TILE * N_CLS),
                     TILE_BYTES, bar_u32[ibuf]);
        }
        issue_tile += stride;

        // ---- wait for this iteration's tile ----
        mbar_wait(bar_u32[buf], phase);

        // ---- per-thread partial max/argmax over 20 classes (sigmoid monotonic) ----
        const float4* my = &sm[buf][row * F4_PER_ROW + part * 5];
        float best = -CUDART_INF_F;
        int   bidx = 0;
        #pragma unroll
        for (int j = 0; j < 5; ++j) {
            float4 v = my[j];
            int b0 = part * 20 + j * 4;
            if (v.x > best) { best = v.x; bidx = b0 + 0; }
            if (v.y > best) { best = v.y; bidx = b0 + 1; }
            if (v.z > best) { best = v.z; bidx = b0 + 2; }
            if (v.w > best) { best = v.w; bidx = b0 + 3; }
        }

        // ---- combine the 4 segment-partials (tie -> lowest class index) ----
        #pragma unroll
        for (int off = 1; off <= 2; off <<= 1) {
            float ob = __shfl_xor_sync(0xffffffffu, best, off);
            int   oi = __shfl_xor_sync(0xffffffffu, bidx, off);
            if (ob > best || (ob == best && oi < bidx)) { best = ob; bidx = oi; }
        }

        // ---- owner lane: bbox decode + confidence + writes ----
        if (part == 0) {
            int loc = (int)(k * TILE) + row;

            float4 bb = bbox4[loc];
            float l  = __expf(bb.x) * 8.0f;
            float tt = __expf(bb.y) * 8.0f;
            float r  = __expf(bb.z) * 8.0f;
            float bo = __expf(bb.w) * 8.0f;

            int h = (loc >> 7) & 127;
            int w =  loc       & 127;

            float4 xywh;
            xywh.x = ((float)w * 8.0f + 4.0f) - (l  - r ) * 0.5f;
            xywh.y = ((float)h * 8.0f + 4.0f) - (tt - bo) * 0.5f;
            xywh.z = l  + r;
            xywh.w = tt + bo;

            float s_ctr = 1.0f / (1.0f + __expf(-center[loc]));
            float s_cls = 1.0f / (1.0f + __expf(-best));

            reinterpret_cast<float4*>(out)[loc] = xywh;
            out[XYWH_ELEMS + loc]               = (float)bidx;
            out[XYWH_ELEMS + N_LOC + loc]       = sqrtf(s_ctr * s_cls);
        }

        // ---- all threads done reading sm[buf] before it is refilled next iter ----
        __syncthreads();

        ++buf;
        if (buf == STAGES) { buf = 0; phase ^= 1; }
    }
}

extern "C" void kernel_launch(void* const* d_in, const int* in_sizes, int n_in,
                              void* d_out, int out_size)
{
    const float* bbox   = (const float*)d_in[0];
    const float* center = (const float*)d_in[1];
    const float* cls    = (const float*)d_in[2];
    float* out = (float*)d_out;

    fcos_decode_kernel<<<GRID, THREADS>>>(
        cls,
        reinterpret_cast<const float4*>(bbox),
        center, out);
}

// round 6
// speedup vs baseline: 1.1175x; 1.1175x over previous
#include <cuda_runtime.h>
#include <cuda_pipeline.h>
#include <math_constants.h>

// FCOS decode — fully warp-decoupled 3-stage cp.async pipelines, no block barriers.
//   inputs  : bbox [16,128,128,4] f32, center [16,128,128,1] f32, cls [16,128,128,80] f32
//   outputs : xywh [16,16384,4] f32 ++ cls_idx [16,16384] (as f32) ++ conf [16,16384] f32

#define N_LOC      (16 * 128 * 128)   // 262144
#define N_CLS      80
#define XYWH_ELEMS (N_LOC * 4)

#define THREADS        128
#define WARPS          (THREADS / 32)            // 4
#define WTILE          8                         // locations per warp-tile
#define F4_PER_ROW     (N_CLS / 4)               // 20
#define F4_PER_WTILE   (WTILE * F4_PER_ROW)      // 160
#define F4_PER_THREAD  (F4_PER_WTILE / 32)       // 5
#define STAGES         3
#define N_WTILES       (N_LOC / WTILE)           // 32768

#define NUM_SMS        148
#define BLOCKS_PER_SM  7
#define GRID           (NUM_SMS * BLOCKS_PER_SM) // 1036

__device__ __forceinline__ float4 fmax4(float4 a, float4 b) {
    float4 r;
    r.x = fmaxf(a.x, b.x); r.y = fmaxf(a.y, b.y);
    r.z = fmaxf(a.z, b.z); r.w = fmaxf(a.w, b.w);
    return r;
}

__global__ __launch_bounds__(THREADS)
void fcos_decode_kernel(const float4* __restrict__ cls4,
                        const float4* __restrict__ bbox4,
                        const float*  __restrict__ center,
                        float* __restrict__ out)
{
    __shared__ float4 sm[WARPS][STAGES][F4_PER_WTILE];   // 30 KB

    const int lane = threadIdx.x & 31;
    const int wid  = threadIdx.x >> 5;
    const int wgid = blockIdx.x * WARPS + wid;           // global warp id
    const int W    = GRID * WARPS;                       // 4144 warps
    const int row  = lane >> 2;   // 0..7 (location within warp-tile)
    const int part = lane & 3;    // 0..3 (20-class segment)

    float4 (*buf)[F4_PER_WTILE] = sm[wid];

    // ---- prologue: issue loads for iterations 0..STAGES-2 ----
    int issue = wgid;
    #pragma unroll
    for (int s = 0; s < STAGES - 1; ++s) {
        if (issue < N_WTILES) {
            const float4* src = cls4 + (size_t)issue * F4_PER_WTILE;
            #pragma unroll
            for (int i = 0; i < F4_PER_THREAD; ++i)
                __pipeline_memcpy_async(&buf[s][lane + 32 * i],
                                        &src[lane + 32 * i], 16);
        }
        __pipeline_commit();
        issue += W;
    }

    int bi = 0;
    for (int k = wgid; k < N_WTILES; k += W) {
        // ---- issue iteration k+STAGES-1 into the slot consumed last iteration ----
        {
            int ib = bi + (STAGES - 1);
            if (ib >= STAGES) ib -= STAGES;
            if (issue < N_WTILES) {
                const float4* src = cls4 + (size_t)issue * F4_PER_WTILE;
                #pragma unroll
                for (int i = 0; i < F4_PER_THREAD; ++i)
                    __pipeline_memcpy_async(&buf[ib][lane + 32 * i],
                                            &src[lane + 32 * i], 16);
            }
            __pipeline_commit();
            issue += W;
        }
        __pipeline_wait_prior(STAGES - 1);   // this iteration's tile complete
        __syncwarp();                        // cross-lane smem visibility

        // ---- load my 20 classes ----
        const float4* my = &buf[bi][row * F4_PER_ROW + part * F4_PER_THREAD];
        float4 v0 = my[0], v1 = my[1], v2 = my[2], v3 = my[3], v4 = my[4];

        // ---- max via shallow FMNMX tree (sigmoid monotonic -> raw logits) ----
        float4 a = fmax4(fmax4(v0, v1), fmax4(v2, v3));
        a = fmax4(a, v4);
        float best = fmaxf(fmaxf(a.x, a.y), fmaxf(a.z, a.w));

        // ---- first index equal to max: independent compares + IMNMX tree ----
        const int b0 = part * 20;
        int c0 = (v0.x == best) ? b0 + 0  : 1023;
        int c1 = (v0.y == best) ? b0 + 1  : 1023;
        int c2 = (v0.z == best) ? b0 + 2  : 1023;
        int c3 = (v0.w == best) ? b0 + 3  : 1023;
        int c4 = (v1.x == best) ? b0 + 4  : 1023;
        int c5 = (v1.y == best) ? b0 + 5  : 1023;
        int c6 = (v1.z == best) ? b0 + 6  : 1023;
        int c7 = (v1.w == best) ? b0 + 7  : 1023;
        int c8 = (v2.x == best) ? b0 + 8  : 1023;
        int c9 = (v2.y == best) ? b0 + 9  : 1023;
        int ca = (v2.z == best) ? b0 + 10 : 1023;
        int cb = (v2.w == best) ? b0 + 11 : 1023;
        int cc = (v3.x == best) ? b0 + 12 : 1023;
        int cd = (v3.y == best) ? b0 + 13 : 1023;
        int ce = (v3.z == best) ? b0 + 14 : 1023;
        int cf = (v3.w == best) ? b0 + 15 : 1023;
        int cg = (v4.x == best) ? b0 + 16 : 1023;
        int ch = (v4.y == best) ? b0 + 17 : 1023;
        int ci = (v4.z == best) ? b0 + 18 : 1023;
        int cj = (v4.w == best) ? b0 + 19 : 1023;
        int bidx = min(min(min(min(c0, c1), min(c2, c3)),
                           min(min(c4, c5), min(c6, c7))),
                       min(min(min(c8, c9), min(ca, cb)),
                           min(min(cc, cd), min(ce, cf))));
        bidx = min(bidx, min(min(cg, ch), min(ci, cj)));

        // ---- combine 4 segment-partials (tie -> lowest class index) ----
        #pragma unroll
        for (int off = 1; off <= 2; off <<= 1) {
            float ob = __shfl_xor_sync(0xffffffffu, best, off);
            int   oi = __shfl_xor_sync(0xffffffffu, bidx, off);
            if (ob > best || (ob == best && oi < bidx)) { best = ob; bidx = oi; }
        }

        // ---- owner lane: bbox decode + confidence + writes ----
        if (part == 0) {
            int loc = k * WTILE + row;

            float4 bb = bbox4[loc];
            float l  = __expf(bb.x) * 8.0f;
            float tt = __expf(bb.y) * 8.0f;
            float r  = __expf(bb.z) * 8.0f;
            float bo = __expf(bb.w) * 8.0f;

            int h = (loc >> 7) & 127;
            int w =  loc       & 127;

            float4 xywh;
            xywh.x = ((float)w * 8.0f + 4.0f) - (l  - r ) * 0.5f;
            xywh.y = ((float)h * 8.0f + 4.0f) - (tt - bo) * 0.5f;
            xywh.z = l  + r;
            xywh.w = tt + bo;

            float s_ctr = 1.0f / (1.0f + __expf(-center[loc]));
            float s_cls = 1.0f / (1.0f + __expf(-best));

            reinterpret_cast<float4*>(out)[loc] = xywh;
            out[XYWH_ELEMS + loc]               = (float)bidx;
            out[XYWH_ELEMS + N_LOC + loc]       = sqrtf(s_ctr * s_cls);
        }

        __syncwarp();   // lanes done reading buf[bi] before next iter refills it
        ++bi;
        if (bi == STAGES) bi = 0;
    }
}

extern "C" void kernel_launch(void* const* d_in, const int* in_sizes, int n_in,
                              void* d_out, int out_size)
{
    const float* bbox   = (const float*)d_in[0];
    const float* center = (const float*)d_in[1];
    const float* cls    = (const float*)d_in[2];
    float* out = (float*)d_out;

    fcos_decode_kernel<<<GRID, THREADS>>>(
        reinterpret_cast<const float4*>(cls),
        reinterpret_cast<const float4*>(bbox),
        center, out);
}

// round 7
// speedup vs baseline: 1.1196x; 1.0019x over previous
#include <cuda_runtime.h>
#include <math_constants.h>
#include <cstdint>

// FCOS decode — warp-decoupled 2-stage cp.async.cg pipelines, 10 blocks/SM.
//   inputs  : bbox [16,128,128,4] f32, center [16,128,128,1] f32, cls [16,128,128,80] f32
//   outputs : xywh [16,16384,4] f32 ++ cls_idx [16,16384] (as f32) ++ conf [16,16384] f32

#define N_LOC      (16 * 128 * 128)   // 262144
#define N_CLS      80
#define XYWH_ELEMS (N_LOC * 4)

#define THREADS        128
#define WARPS          (THREADS / 32)            // 4
#define WTILE          8                         // locations per warp-tile
#define F4_PER_ROW     (N_CLS / 4)               // 20
#define F4_PER_WTILE   (WTILE * F4_PER_ROW)      // 160 (2.56 KB)
#define F4_PER_THREAD  (F4_PER_WTILE / 32)       // 5
#define STAGES         2
#define N_WTILES       (N_LOC / WTILE)           // 32768

#define NUM_SMS        148
#define BLOCKS_PER_SM  10
#define GRID           (NUM_SMS * BLOCKS_PER_SM) // 1480

__device__ __forceinline__ float4 fmax4(float4 a, float4 b) {
    float4 r;
    r.x = fmaxf(a.x, b.x); r.y = fmaxf(a.y, b.y);
    r.z = fmaxf(a.z, b.z); r.w = fmaxf(a.w, b.w);
    return r;
}

__device__ __forceinline__ void cp_cg16(void* smem_dst, const void* gsrc) {
    unsigned d = (unsigned)__cvta_generic_to_shared(smem_dst);
    asm volatile("cp.async.cg.shared.global [%0], [%1], 16;"
                 :: "r"(d), "l"(gsrc) : "memory");
}
__device__ __forceinline__ void cp_commit() {
    asm volatile("cp.async.commit_group;" ::: "memory");
}
__device__ __forceinline__ void cp_wait1() {
    asm volatile("cp.async.wait_group 1;" ::: "memory");
}

__global__ __launch_bounds__(THREADS, BLOCKS_PER_SM)
void fcos_decode_kernel(const float4* __restrict__ cls4,
                        const float4* __restrict__ bbox4,
                        const float*  __restrict__ center,
                        float* __restrict__ out)
{
    __shared__ float4 sm[WARPS][STAGES][F4_PER_WTILE];   // 20 KB

    const int lane = threadIdx.x & 31;
    const int wid  = threadIdx.x >> 5;
    const int wgid = blockIdx.x * WARPS + wid;           // global warp id
    const int W    = GRID * WARPS;                       // 5920 warps
    const int row  = lane >> 2;   // 0..7 (location within warp-tile)
    const int part = lane & 3;    // 0..3 (20-class segment)

    float4 (*buf)[F4_PER_WTILE] = sm[wid];

    // ---- prologue: issue tile for iteration 0 ----
    int issue = wgid;
    if (issue < N_WTILES) {
        const float4* src = cls4 + (size_t)issue * F4_PER_WTILE;
        #pragma unroll
        for (int i = 0; i < F4_PER_THREAD; ++i)
            cp_cg16(&buf[0][lane + 32 * i], &src[lane + 32 * i]);
    }
    cp_commit();
    issue += W;

    int bi = 0;
    for (int k = wgid; k < N_WTILES; k += W) {
        // ---- issue next iteration's tile into the other buffer ----
        if (issue < N_WTILES) {
            const float4* src = cls4 + (size_t)issue * F4_PER_WTILE;
            #pragma unroll
            for (int i = 0; i < F4_PER_THREAD; ++i)
                cp_cg16(&buf[bi ^ 1][lane + 32 * i], &src[lane + 32 * i]);
        }
        cp_commit();
        issue += W;

        cp_wait1();     // current tile's group complete (next still in flight)
        __syncwarp();   // cross-lane smem visibility

        // ---- load my 20 classes ----
        const float4* my = &buf[bi][row * F4_PER_ROW + part * F4_PER_THREAD];
        float4 v0 = my[0], v1 = my[1], v2 = my[2], v3 = my[3], v4 = my[4];

        // ---- max via shallow FMNMX tree (sigmoid monotonic -> raw logits) ----
        float4 a = fmax4(fmax4(v0, v1), fmax4(v2, v3));
        a = fmax4(a, v4);
        float best = fmaxf(fmaxf(a.x, a.y), fmaxf(a.z, a.w));

        // ---- first index equal to max: independent compares + min tree ----
        const int b0 = part * 20;
        int c0 = (v0.x == best) ? b0 + 0  : 1023;
        int c1 = (v0.y == best) ? b0 + 1  : 1023;
        int c2 = (v0.z == best) ? b0 + 2  : 1023;
        int c3 = (v0.w == best) ? b0 + 3  : 1023;
        int c4 = (v1.x == best) ? b0 + 4  : 1023;
        int c5 = (v1.y == best) ? b0 + 5  : 1023;
        int c6 = (v1.z == best) ? b0 + 6  : 1023;
        int c7 = (v1.w == best) ? b0 + 7  : 1023;
        int c8 = (v2.x == best) ? b0 + 8  : 1023;
        int c9 = (v2.y == best) ? b0 + 9  : 1023;
        int ca = (v2.z == best) ? b0 + 10 : 1023;
        int cb = (v2.w == best) ? b0 + 11 : 1023;
        int cc = (v3.x == best) ? b0 + 12 : 1023;
        int cd = (v3.y == best) ? b0 + 13 : 1023;
        int ce = (v3.z == best) ? b0 + 14 : 1023;
        int cf = (v3.w == best) ? b0 + 15 : 1023;
        int cg = (v4.x == best) ? b0 + 16 : 1023;
        int ch = (v4.y == best) ? b0 + 17 : 1023;
        int ci = (v4.z == best) ? b0 + 18 : 1023;
        int cj = (v4.w == best) ? b0 + 19 : 1023;
        int bidx = min(min(min(min(c0, c1), min(c2, c3)),
                           min(min(c4, c5), min(c6, c7))),
                       min(min(min(c8, c9), min(ca, cb)),
                           min(min(cc, cd), min(ce, cf))));
        bidx = min(bidx, min(min(cg, ch), min(ci, cj)));

        // ---- combine 4 segment-partials (tie -> lowest class index) ----
        #pragma unroll
        for (int off = 1; off <= 2; off <<= 1) {
            float ob = __shfl_xor_sync(0xffffffffu, best, off);
            int   oi = __shfl_xor_sync(0xffffffffu, bidx, off);
            if (ob > best || (ob == best && oi < bidx)) { best = ob; bidx = oi; }
        }

        // ---- owner lane: bbox decode + confidence + writes ----
        if (part == 0) {
            int loc = k * WTILE + row;

            float4 bb = __ldcs(&bbox4[loc]);
            float l  = __expf(bb.x) * 8.0f;
            float tt = __expf(bb.y) * 8.0f;
            float r  = __expf(bb.z) * 8.0f;
            float bo = __expf(bb.w) * 8.0f;

            int h = (loc >> 7) & 127;
            int w =  loc       & 127;

            float4 xywh;
            xywh.x = ((float)w * 8.0f + 4.0f) - (l  - r ) * 0.5f;
            xywh.y = ((float)h * 8.0f + 4.0f) - (tt - bo) * 0.5f;
            xywh.z = l  + r;
            xywh.w = tt + bo;

            float s_ctr = 1.0f / (1.0f + __expf(-__ldcs(&center[loc])));
            float s_cls = 1.0f / (1.0f + __expf(-best));

            __stcs(&reinterpret_cast<float4*>(out)[loc], xywh);
            __stcs(&out[XYWH_ELEMS + loc], (float)bidx);
            __stcs(&out[XYWH_ELEMS + N_LOC + loc], sqrtf(s_ctr * s_cls));
        }

        __syncwarp();   // lanes done reading buf[bi] before next iter refills it
        bi ^= 1;
    }
}

extern "C" void kernel_launch(void* const* d_in, const int* in_sizes, int n_in,
                              void* d_out, int out_size)
{
    const float* bbox   = (const float*)d_in[0];
    const float* center = (const float*)d_in[1];
    const float* cls    = (const float*)d_in[2];
    float* out = (float*)d_out;

    fcos_decode_kernel<<<GRID, THREADS>>>(
        reinterpret_cast<const float4*>(cls),
        reinterpret_cast<const float4*>(bbox),
        center, out);
}